// round 1
// baseline (speedup 1.0000x reference)
#include <cuda_runtime.h>
#include <cuda_bf16.h>
#include <math.h>

#define BATCH 2
#define SEQ   2048
#define DMODEL 2048
#define NH    32
#define NKV   8
#define HD    64

// Scratch (device globals; no allocation allowed)
__device__ float g_Q[BATCH * SEQ * NH * HD];   // [B,S,H,HD]
__device__ float g_K[BATCH * SEQ * NKV * HD];  // [B,S,KV,HD]
__device__ float g_V[BATCH * SEQ * NKV * HD];  // [B,S,KV,HD]
__device__ float g_O[BATCH * SEQ * NH * HD];   // [B,S,H,HD]

// ---------------------------------------------------------------------------
// SGEMM: C[M,N] = A[M,K] @ B[K,N], all row-major, M%128==0, N%128==0, K%16==0
// 128x128 tile, BK=16, 256 threads, 8x8 per thread.
// A stored transposed in smem (At[k][m]) with XOR-4 swizzle (col ^= k&12) so
// inner-loop reads are row-uniform (conflict-free); B stored natural.
// ---------------------------------------------------------------------------
__global__ __launch_bounds__(256) void sgemm128(
    const float* __restrict__ A, const float* __restrict__ B,
    float* __restrict__ C, int M, int N, int K)
{
    __shared__ float At[16 * 128];
    __shared__ float Bs[16 * 128];

    const int tid = threadIdx.x;
    const int tx = tid & 15;        // 0..15 -> N
    const int ty = tid >> 4;        // 0..15 -> M
    const int m0 = blockIdx.y * 128;
    const int n0 = blockIdx.x * 128;

    float acc[8][8];
#pragma unroll
    for (int i = 0; i < 8; ++i)
#pragma unroll
        for (int j = 0; j < 8; ++j) acc[i][j] = 0.0f;

    for (int k0 = 0; k0 < K; k0 += 16) {
        __syncthreads();
        // Load A tile: 128x16 = 512 float4, 2 per thread, transpose+swizzle
#pragma unroll
        for (int t = 0; t < 2; ++t) {
            int f4i = tid + t * 256;            // 0..511
            int m = f4i >> 2;                   // 0..127
            int kq = f4i & 3;                   // 0..3
            float4 v = *(const float4*)(A + (size_t)(m0 + m) * K + k0 + kq * 4);
            int r = kq * 4;
            int X = r & 12;                     // same for r..r+3
            At[(r + 0) * 128 + (m ^ X)] = v.x;
            At[(r + 1) * 128 + (m ^ X)] = v.y;
            At[(r + 2) * 128 + (m ^ X)] = v.z;
            At[(r + 3) * 128 + (m ^ X)] = v.w;
        }
        // Load B tile: 16x128 = 512 float4
#pragma unroll
        for (int t = 0; t < 2; ++t) {
            int f4i = tid + t * 256;
            int k = f4i >> 5;                   // 0..15
            int nq = f4i & 31;                  // 0..31
            float4 v = *(const float4*)(B + (size_t)(k0 + k) * N + n0 + nq * 4);
            *(float4*)&Bs[k * 128 + nq * 4] = v;
        }
        __syncthreads();

#pragma unroll
        for (int kk = 0; kk < 16; ++kk) {
            int X = kk & 12;
            int ca = (ty * 8) ^ X;
            float4 a0 = *(const float4*)&At[kk * 128 + ca];
            float4 a1 = *(const float4*)&At[kk * 128 + (ca ^ 4)];
            float4 b0 = *(const float4*)&Bs[kk * 128 + tx * 8];
            float4 b1 = *(const float4*)&Bs[kk * 128 + tx * 8 + 4];
            float aa[8] = {a0.x, a0.y, a0.z, a0.w, a1.x, a1.y, a1.z, a1.w};
            float bb[8] = {b0.x, b0.y, b0.z, b0.w, b1.x, b1.y, b1.z, b1.w};
#pragma unroll
            for (int i = 0; i < 8; ++i)
#pragma unroll
                for (int j = 0; j < 8; ++j)
                    acc[i][j] = fmaf(aa[i], bb[j], acc[i][j]);
        }
    }

#pragma unroll
    for (int i = 0; i < 8; ++i) {
        float* crow = C + (size_t)(m0 + ty * 8 + i) * N + n0 + tx * 8;
        *(float4*)crow = make_float4(acc[i][0], acc[i][1], acc[i][2], acc[i][3]);
        *(float4*)(crow + 4) = make_float4(acc[i][4], acc[i][5], acc[i][6], acc[i][7]);
    }
}

// ---------------------------------------------------------------------------
// RoPE in-place on [B,S,nheads,HD]. One thread per (b,s,h,d<32) pair.
// ---------------------------------------------------------------------------
__global__ void rope_kernel(float* __restrict__ T, int nheads, int total)
{
    int idx = blockIdx.x * blockDim.x + threadIdx.x;
    if (idx >= total) return;
    int d = idx & 31;
    int t = idx >> 5;              // (b*S+s)*nheads + h
    int u = t / nheads;            // b*S + s
    int s = u % SEQ;

    float invf = 1.0f / powf(10000.0f, (float)d * (1.0f / 32.0f));
    float ang = (float)s * invf;
    float sn, cs;
    sincosf(ang, &sn, &cs);

    float* p = T + (size_t)t * HD + d;
    float x0 = p[0];
    float x1 = p[32];
    p[0]  = x0 * cs - x1 * sn;
    p[32] = x1 * cs + x0 * sn;
}

// ---------------------------------------------------------------------------
// Causal flash attention, GQA (4 q-heads per kv-head).
// grid = (S/64, NH, B), 64 threads, each thread computes 8x8 of S and 8x8 of O.
// Shared tiles stored reduction-major (Qt[d][m], Kt[d][n], Pt[n][m]) with
// XOR-4 swizzle so inner-loop reads are row-uniform. Pt aliases Kt.
// ---------------------------------------------------------------------------
__global__ __launch_bounds__(64) void attn_kernel(
    const float* __restrict__ Q, const float* __restrict__ K,
    const float* __restrict__ V, float* __restrict__ O)
{
    __shared__ float Qt[64 * 64];  // Qt[d][m]
    __shared__ float KP[64 * 64];  // Kt[d][n], then Pt[n][m]
    __shared__ float Vs[64 * 64];  // Vs[n][d]

    const int tid = threadIdx.x;
    const int tx = tid & 7;        // 0..7
    const int ty = tid >> 3;       // 0..7
    const int qt = blockIdx.x;
    const int h  = blockIdx.y;
    const int b  = blockIdx.z;
    const int g  = h >> 2;
    const int q0 = qt * 64;

    const float* Qbase = Q + ((size_t)((size_t)b * SEQ + q0) * NH + h) * HD;

    // Load Q tile (transpose + swizzle)
#pragma unroll
    for (int t = 0; t < 16; ++t) {
        int f4i = tid + t * 64;
        int m = f4i >> 4, dq = f4i & 15;
        float4 v = *(const float4*)(Qbase + (size_t)m * (NH * HD) + dq * 4);
        int r = dq * 4;
        int X = r & 60;
        Qt[(r + 0) * 64 + (m ^ X)] = v.x;
        Qt[(r + 1) * 64 + (m ^ X)] = v.y;
        Qt[(r + 2) * 64 + (m ^ X)] = v.z;
        Qt[(r + 3) * 64 + (m ^ X)] = v.w;
    }

    float mi[8], li[8], o[8][8];
#pragma unroll
    for (int i = 0; i < 8; ++i) {
        mi[i] = -1e30f; li[i] = 0.0f;
#pragma unroll
        for (int j = 0; j < 8; ++j) o[i][j] = 0.0f;
    }

    for (int jt = 0; jt <= qt; ++jt) {
        __syncthreads();   // prior iteration readers done (and Qt load on iter 0)
        const int n0 = jt * 64;
        const float* Kbase = K + ((size_t)((size_t)b * SEQ + n0) * NKV + g) * HD;
        const float* Vbase = V + ((size_t)((size_t)b * SEQ + n0) * NKV + g) * HD;
#pragma unroll
        for (int t = 0; t < 16; ++t) {
            int f4i = tid + t * 64;
            int n = f4i >> 4, dq = f4i & 15;
            float4 kv = *(const float4*)(Kbase + (size_t)n * (NKV * HD) + dq * 4);
            int r = dq * 4;
            int X = r & 60;
            KP[(r + 0) * 64 + (n ^ X)] = kv.x;
            KP[(r + 1) * 64 + (n ^ X)] = kv.y;
            KP[(r + 2) * 64 + (n ^ X)] = kv.z;
            KP[(r + 3) * 64 + (n ^ X)] = kv.w;
            float4 vv = *(const float4*)(Vbase + (size_t)n * (NKV * HD) + dq * 4);
            *(float4*)&Vs[n * 64 + dq * 4] = vv;
        }
        __syncthreads();

        // S = Q @ K^T  (s[j][i] = S[m=ty*8+i][n=tx*8+j])
        float s[8][8];
#pragma unroll
        for (int j = 0; j < 8; ++j)
#pragma unroll
            for (int i = 0; i < 8; ++i) s[j][i] = 0.0f;

#pragma unroll 4
        for (int d = 0; d < 64; ++d) {
            int X = d & 60;
            const float* qr = &Qt[d * 64];
            const float* kr = &KP[d * 64];
            int ca = (ty * 8) ^ X;
            int cb = (tx * 8) ^ X;
            float4 a0 = *(const float4*)(qr + ca);
            float4 a1 = *(const float4*)(qr + (ca ^ 4));
            float4 b0 = *(const float4*)(kr + cb);
            float4 b1 = *(const float4*)(kr + (cb ^ 4));
            float aa[8] = {a0.x, a0.y, a0.z, a0.w, a1.x, a1.y, a1.z, a1.w};
            float bb[8] = {b0.x, b0.y, b0.z, b0.w, b1.x, b1.y, b1.z, b1.w};
#pragma unroll
            for (int j = 0; j < 8; ++j)
#pragma unroll
                for (int i = 0; i < 8; ++i)
                    s[j][i] = fmaf(aa[i], bb[j], s[j][i]);
        }

        const bool diag = (jt == qt);
        // scale, mask, online softmax per row i
#pragma unroll
        for (int i = 0; i < 8; ++i) {
            float mloc = -1e30f;
#pragma unroll
            for (int j = 0; j < 8; ++j) {
                float v = s[j][i] * 0.125f;
                if (diag && (tx * 8 + j) > (ty * 8 + i)) v = -1e30f;
                s[j][i] = v;
                mloc = fmaxf(mloc, v);
            }
            mloc = fmaxf(mloc, __shfl_xor_sync(0xffffffffu, mloc, 4));
            mloc = fmaxf(mloc, __shfl_xor_sync(0xffffffffu, mloc, 2));
            mloc = fmaxf(mloc, __shfl_xor_sync(0xffffffffu, mloc, 1));
            float mnew = fmaxf(mi[i], mloc);
            float sf = __expf(mi[i] - mnew);
            float ps = 0.0f;
#pragma unroll
            for (int j = 0; j < 8; ++j) {
                float p = __expf(s[j][i] - mnew);
                s[j][i] = p;
                ps += p;
            }
            ps += __shfl_xor_sync(0xffffffffu, ps, 4);
            ps += __shfl_xor_sync(0xffffffffu, ps, 2);
            ps += __shfl_xor_sync(0xffffffffu, ps, 1);
            li[i] = li[i] * sf + ps;
            mi[i] = mnew;
#pragma unroll
            for (int dj = 0; dj < 8; ++dj) o[i][dj] *= sf;
        }

        __syncthreads();   // everyone done reading Kt
        // Store P transposed: Pt[n][m] (aliases Kt), swizzled
#pragma unroll
        for (int j = 0; j < 8; ++j) {
            int n = tx * 8 + j;
            int X = n & 60;
            int c = (ty * 8) ^ X;
            *(float4*)&KP[n * 64 + c] =
                make_float4(s[j][0], s[j][1], s[j][2], s[j][3]);
            *(float4*)&KP[n * 64 + (c ^ 4)] =
                make_float4(s[j][4], s[j][5], s[j][6], s[j][7]);
        }
        __syncthreads();

        // O += P @ V
#pragma unroll 4
        for (int n = 0; n < 64; ++n) {
            int X = n & 60;
            int ca = (ty * 8) ^ X;
            float4 p0 = *(const float4*)&KP[n * 64 + ca];
            float4 p1 = *(const float4*)&KP[n * 64 + (ca ^ 4)];
            float4 v0 = *(const float4*)&Vs[n * 64 + tx * 8];
            float4 v1 = *(const float4*)&Vs[n * 64 + tx * 8 + 4];
            float pp[8] = {p0.x, p0.y, p0.z, p0.w, p1.x, p1.y, p1.z, p1.w};
            float vv[8] = {v0.x, v0.y, v0.z, v0.w, v1.x, v1.y, v1.z, v1.w};
#pragma unroll
            for (int i = 0; i < 8; ++i)
#pragma unroll
                for (int dj = 0; dj < 8; ++dj)
                    o[i][dj] = fmaf(pp[i], vv[dj], o[i][dj]);
        }
    }

    // Epilogue: normalize and store [B,S,H,HD]
    float* Obase = O + ((size_t)((size_t)b * SEQ + q0) * NH + h) * HD;
#pragma unroll
    for (int i = 0; i < 8; ++i) {
        float inv = 1.0f / li[i];
        float* orow = Obase + (size_t)(ty * 8 + i) * (NH * HD) + tx * 8;
        *(float4*)orow = make_float4(o[i][0] * inv, o[i][1] * inv,
                                     o[i][2] * inv, o[i][3] * inv);
        *(float4*)(orow + 4) = make_float4(o[i][4] * inv, o[i][5] * inv,
                                           o[i][6] * inv, o[i][7] * inv);
    }
}

// ---------------------------------------------------------------------------
extern "C" void kernel_launch(void* const* d_in, const int* in_sizes, int n_in,
                              void* d_out, int out_size)
{
    const float* x  = (const float*)d_in[0];
    const float* Wq = (const float*)d_in[1];
    const float* Wk = (const float*)d_in[2];
    const float* Wv = (const float*)d_in[3];
    const float* Wo = (const float*)d_in[4];
    float* out = (float*)d_out;

    float *Q, *K, *V, *Oc;
    cudaGetSymbolAddress((void**)&Q,  g_Q);
    cudaGetSymbolAddress((void**)&K,  g_K);
    cudaGetSymbolAddress((void**)&V,  g_V);
    cudaGetSymbolAddress((void**)&Oc, g_O);

    const int M = BATCH * SEQ;  // 4096

    // Projections
    sgemm128<<<dim3((NH * HD) / 128, M / 128), 256>>>(x, Wq, Q, M, NH * HD, DMODEL);
    sgemm128<<<dim3((NKV * HD) / 128, M / 128), 256>>>(x, Wk, K, M, NKV * HD, DMODEL);
    sgemm128<<<dim3((NKV * HD) / 128, M / 128), 256>>>(x, Wv, V, M, NKV * HD, DMODEL);

    // RoPE
    {
        int totQ = BATCH * SEQ * NH * (HD / 2);
        int totK = BATCH * SEQ * NKV * (HD / 2);
        rope_kernel<<<(totQ + 255) / 256, 256>>>(Q, NH, totQ);
        rope_kernel<<<(totK + 255) / 256, 256>>>(K, NKV, totK);
    }

    // Attention
    attn_kernel<<<dim3(SEQ / 64, NH, BATCH), 64>>>(Q, K, V, Oc);

    // Output projection
    sgemm128<<<dim3(DMODEL / 128, M / 128), 256>>>(Oc, Wo, out, M, DMODEL, DMODEL);
}

// round 3
// speedup vs baseline: 1.5741x; 1.5741x over previous
#include <cuda_runtime.h>
#include <cuda_bf16.h>
#include <math.h>
#include <stdint.h>

#define BATCH 2
#define SEQ   2048
#define DMODEL 2048
#define NH    32
#define NKV   8
#define HD    64
#define MTOT  (BATCH * SEQ)          // 4096

// ---------------- scratch (device globals; no allocation allowed) ----------
__device__ float g_Q[MTOT * NH * HD];    // [B,S,H,HD]
__device__ float g_K[MTOT * NKV * HD];   // [B,S,KV,HD]
__device__ float g_V[MTOT * NKV * HD];   // [B,S,KV,HD]
__device__ float g_O[MTOT * NH * HD];    // [B,S,H,HD]

// bf16 split buffers
__device__ __nv_bfloat16 g_xhi[MTOT * DMODEL];
__device__ __nv_bfloat16 g_xlo[MTOT * DMODEL];
__device__ __nv_bfloat16 g_wqt_hi[DMODEL * DMODEL];  // [N, K] (transposed)
__device__ __nv_bfloat16 g_wqt_lo[DMODEL * DMODEL];
__device__ __nv_bfloat16 g_wkt_hi[(NKV * HD) * DMODEL];
__device__ __nv_bfloat16 g_wkt_lo[(NKV * HD) * DMODEL];
__device__ __nv_bfloat16 g_wvt_hi[(NKV * HD) * DMODEL];
__device__ __nv_bfloat16 g_wvt_lo[(NKV * HD) * DMODEL];
__device__ __nv_bfloat16 g_wot_hi[DMODEL * DMODEL];
__device__ __nv_bfloat16 g_wot_lo[DMODEL * DMODEL];

// ---------------- PTX helpers ----------------------------------------------
__device__ __forceinline__ uint32_t smem_u32(const void* p) {
    uint32_t a;
    asm("{ .reg .u64 t; cvta.to.shared.u64 t, %1; cvt.u32.u64 %0, t; }"
        : "=r"(a) : "l"(p));
    return a;
}
__device__ __forceinline__ void cp_async16(uint32_t saddr, const void* gaddr) {
    asm volatile("cp.async.cg.shared.global [%0], [%1], 16;"
                 :: "r"(saddr), "l"(gaddr) : "memory");
}
__device__ __forceinline__ void cp_commit() {
    asm volatile("cp.async.commit_group;" ::: "memory");
}
template <int N>
__device__ __forceinline__ void cp_wait() {
    asm volatile("cp.async.wait_group %0;" :: "n"(N) : "memory");
}
__device__ __forceinline__ void ldsm_x4(uint32_t& r0, uint32_t& r1, uint32_t& r2,
                                        uint32_t& r3, uint32_t addr) {
    asm volatile("ldmatrix.sync.aligned.m8n8.x4.shared.b16 {%0,%1,%2,%3}, [%4];"
                 : "=r"(r0), "=r"(r1), "=r"(r2), "=r"(r3) : "r"(addr));
}
__device__ __forceinline__ void ldsm_x2(uint32_t& r0, uint32_t& r1, uint32_t addr) {
    asm volatile("ldmatrix.sync.aligned.m8n8.x2.shared.b16 {%0,%1}, [%2];"
                 : "=r"(r0), "=r"(r1) : "r"(addr));
}
__device__ __forceinline__ void mma_bf16(float* c, const uint32_t* a, const uint32_t* b) {
    asm volatile(
        "mma.sync.aligned.m16n8k16.row.col.f32.bf16.bf16.f32 "
        "{%0,%1,%2,%3}, {%4,%5,%6,%7}, {%8,%9}, {%0,%1,%2,%3};"
        : "+f"(c[0]), "+f"(c[1]), "+f"(c[2]), "+f"(c[3])
        : "r"(a[0]), "r"(a[1]), "r"(a[2]), "r"(a[3]), "r"(b[0]), "r"(b[1]));
}

// ---------------------------------------------------------------------------
// Split fp32 -> bf16 hi/lo (elementwise)
// ---------------------------------------------------------------------------
__global__ void split_kernel(const float* __restrict__ X,
                             __nv_bfloat16* __restrict__ hi,
                             __nv_bfloat16* __restrict__ lo, int n)
{
    int i = blockIdx.x * blockDim.x + threadIdx.x;
    if (i >= n) return;
    float x = X[i];
    __nv_bfloat16 h = __float2bfloat16(x);
    hi[i] = h;
    lo[i] = __float2bfloat16(x - __bfloat162float(h));
}

// ---------------------------------------------------------------------------
// Transpose + split: W[K,N] fp32 -> Th,Tl [N,K] bf16
// ---------------------------------------------------------------------------
__global__ void splitT_kernel(const float* __restrict__ W,
                              __nv_bfloat16* __restrict__ Th,
                              __nv_bfloat16* __restrict__ Tl, int Kd, int Nd)
{
    __shared__ float t[32][33];
    int k0 = blockIdx.y * 32, n0 = blockIdx.x * 32;
    int tx = threadIdx.x, ty = threadIdx.y;  // 32 x 8
#pragma unroll
    for (int r = ty; r < 32; r += 8)
        t[r][tx] = W[(size_t)(k0 + r) * Nd + n0 + tx];
    __syncthreads();
#pragma unroll
    for (int r = ty; r < 32; r += 8) {
        float x = t[tx][r];                   // element (k = k0+tx, n = n0+r)
        __nv_bfloat16 h = __float2bfloat16(x);
        size_t o = (size_t)(n0 + r) * Kd + k0 + tx;
        Th[o] = h;
        Tl[o] = __float2bfloat16(x - __bfloat162float(h));
    }
}

// ---------------------------------------------------------------------------
// mma.sync bf16x3 GEMM: C[M,N] = A[M,K] @ Bt[N,K]^T, fp32 accum.
// CTA tile 128x128x32, 8 warps (2 M x 4 N), warp tile 64x32.
// Smem rows pitched 80B (5*16B) -> ldmatrix conflict-free. cp.async 2-stage.
// ---------------------------------------------------------------------------
#define BK     32
#define PITCH  80                        // bytes per smem row (32 bf16 + pad)
#define TILE_B (128 * PITCH)             // 10240 B
#define STAGE_B (4 * TILE_B)             // Ah, Al, Bh, Bl
#define GEMM_SMEM (2 * STAGE_B)          // 81920 B

__global__ __launch_bounds__(256, 1)
void gemm_mma(const __nv_bfloat16* __restrict__ Ah, const __nv_bfloat16* __restrict__ Al,
              const __nv_bfloat16* __restrict__ Bh, const __nv_bfloat16* __restrict__ Bl,
              float* __restrict__ C, int M, int N, int K)
{
    extern __shared__ char sm[];
    const int tid  = threadIdx.x;
    const int lane = tid & 31;
    const int wid  = tid >> 5;
    const int wm   = wid & 1;            // 0..1  (M)
    const int wn   = wid >> 1;           // 0..3  (N)
    const int m0 = blockIdx.y * 128;
    const int n0 = blockIdx.x * 128;

    const __nv_bfloat16* srcs[4] = {Ah, Al, Bh, Bl};
    const int r0s[4] = {m0, m0, n0, n0};

    float acc[4][4][4];
#pragma unroll
    for (int i = 0; i < 4; ++i)
#pragma unroll
        for (int j = 0; j < 4; ++j)
#pragma unroll
            for (int q = 0; q < 4; ++q) acc[i][j][q] = 0.0f;

    const int nc = K / BK;

    // prologue: load chunk 0 into stage 0
    {
        char* st = sm;
#pragma unroll
        for (int t = 0; t < 4; ++t) {
            const __nv_bfloat16* src = srcs[t];
            const int r0 = r0s[t];
            char* dst = st + t * TILE_B;
#pragma unroll
            for (int u = 0; u < 2; ++u) {
                int v = tid + u * 256;           // 0..511
                int row = v >> 2, q = v & 3;
                cp_async16(smem_u32(dst + row * PITCH + q * 16),
                           src + (size_t)(r0 + row) * K + q * 8);
            }
        }
        cp_commit();
    }

    for (int c = 0; c < nc; ++c) {
        if (c + 1 < nc) {
            char* st = sm + ((c + 1) & 1) * STAGE_B;
            const int k0 = (c + 1) * BK;
#pragma unroll
            for (int t = 0; t < 4; ++t) {
                const __nv_bfloat16* src = srcs[t];
                const int r0 = r0s[t];
                char* dst = st + t * TILE_B;
#pragma unroll
                for (int u = 0; u < 2; ++u) {
                    int v = tid + u * 256;
                    int row = v >> 2, q = v & 3;
                    cp_async16(smem_u32(dst + row * PITCH + q * 16),
                               src + (size_t)(r0 + row) * K + k0 + q * 8);
                }
            }
            cp_commit();
            cp_wait<1>();
        } else {
            cp_wait<0>();
        }
        __syncthreads();

        char* st = sm + (c & 1) * STAGE_B;
        char* sAh = st;
        char* sAl = st + TILE_B;
        char* sBh = st + 2 * TILE_B;
        char* sBl = st + 3 * TILE_B;

#pragma unroll
        for (int ks = 0; ks < 2; ++ks) {
            // A fragments (hi + lo): 4 m-tiles of 16 rows
            uint32_t ah[4][4], al[4][4];
            const int arow = wm * 64 + (lane & 15);
            const int achk = ks * 2 + (lane >> 4);
#pragma unroll
            for (int i = 0; i < 4; ++i) {
                uint32_t off = (uint32_t)((arow + i * 16) * PITCH + achk * 16);
                ldsm_x4(ah[i][0], ah[i][1], ah[i][2], ah[i][3], smem_u32(sAh + off));
                ldsm_x4(al[i][0], al[i][1], al[i][2], al[i][3], smem_u32(sAl + off));
            }
            // B fragments (hi + lo): 4 n-tiles of 8 rows
            uint32_t bh[4][2], bl[4][2];
            const int brow = wn * 32 + (lane & 7);
            const int bchk = ks * 2 + ((lane >> 3) & 1);
#pragma unroll
            for (int j = 0; j < 4; ++j) {
                uint32_t off = (uint32_t)((brow + j * 8) * PITCH + bchk * 16);
                ldsm_x2(bh[j][0], bh[j][1], smem_u32(sBh + off));
                ldsm_x2(bl[j][0], bl[j][1], smem_u32(sBl + off));
            }
#pragma unroll
            for (int i = 0; i < 4; ++i)
#pragma unroll
                for (int j = 0; j < 4; ++j) {
                    mma_bf16(acc[i][j], ah[i], bh[j]);
                    mma_bf16(acc[i][j], ah[i], bl[j]);
                    mma_bf16(acc[i][j], al[i], bh[j]);
                }
        }
        __syncthreads();
    }

    // Epilogue
#pragma unroll
    for (int i = 0; i < 4; ++i) {
        int row = m0 + wm * 64 + i * 16 + (lane >> 2);
#pragma unroll
        for (int j = 0; j < 4; ++j) {
            int col = n0 + wn * 32 + j * 8 + (lane & 3) * 2;
            *(float2*)(C + (size_t)row * N + col) =
                make_float2(acc[i][j][0], acc[i][j][1]);
            *(float2*)(C + (size_t)(row + 8) * N + col) =
                make_float2(acc[i][j][2], acc[i][j][3]);
        }
    }
}

// ---------------------------------------------------------------------------
// RoPE in-place on [B,S,nheads,HD]. One thread per (b,s,h,d<32) pair.
// ---------------------------------------------------------------------------
__global__ void rope_kernel(float* __restrict__ T, int nheads, int total)
{
    int idx = blockIdx.x * blockDim.x + threadIdx.x;
    if (idx >= total) return;
    int d = idx & 31;
    int t = idx >> 5;
    int u = t / nheads;
    int s = u % SEQ;

    float invf = 1.0f / powf(10000.0f, (float)d * (1.0f / 32.0f));
    float ang = (float)s * invf;
    float sn, cs;
    sincosf(ang, &sn, &cs);

    float* p = T + (size_t)t * HD + d;
    float x0 = p[0];
    float x1 = p[32];
    p[0]  = x0 * cs - x1 * sn;
    p[32] = x1 * cs + x0 * sn;
}

// ---------------------------------------------------------------------------
// Causal flash attention, GQA (fp32 SIMT)
// ---------------------------------------------------------------------------
__global__ __launch_bounds__(64) void attn_kernel(
    const float* __restrict__ Q, const float* __restrict__ K,
    const float* __restrict__ V, float* __restrict__ O)
{
    __shared__ float Qt[64 * 64];
    __shared__ float KP[64 * 64];
    __shared__ float Vs[64 * 64];

    const int tid = threadIdx.x;
    const int tx = tid & 7;
    const int ty = tid >> 3;
    const int qt = blockIdx.x;
    const int h  = blockIdx.y;
    const int b  = blockIdx.z;
    const int g  = h >> 2;
    const int q0 = qt * 64;

    const float* Qbase = Q + ((size_t)((size_t)b * SEQ + q0) * NH + h) * HD;

#pragma unroll
    for (int t = 0; t < 16; ++t) {
        int f4i = tid + t * 64;
        int m = f4i >> 4, dq = f4i & 15;
        float4 v = *(const float4*)(Qbase + (size_t)m * (NH * HD) + dq * 4);
        int r = dq * 4;
        int X = r & 60;
        Qt[(r + 0) * 64 + (m ^ X)] = v.x;
        Qt[(r + 1) * 64 + (m ^ X)] = v.y;
        Qt[(r + 2) * 64 + (m ^ X)] = v.z;
        Qt[(r + 3) * 64 + (m ^ X)] = v.w;
    }

    float mi[8], li[8], o[8][8];
#pragma unroll
    for (int i = 0; i < 8; ++i) {
        mi[i] = -1e30f; li[i] = 0.0f;
#pragma unroll
        for (int j = 0; j < 8; ++j) o[i][j] = 0.0f;
    }

    for (int jt = 0; jt <= qt; ++jt) {
        __syncthreads();
        const int n0 = jt * 64;
        const float* Kbase = K + ((size_t)((size_t)b * SEQ + n0) * NKV + g) * HD;
        const float* Vbase = V + ((size_t)((size_t)b * SEQ + n0) * NKV + g) * HD;
#pragma unroll
        for (int t = 0; t < 16; ++t) {
            int f4i = tid + t * 64;
            int n = f4i >> 4, dq = f4i & 15;
            float4 kv = *(const float4*)(Kbase + (size_t)n * (NKV * HD) + dq * 4);
            int r = dq * 4;
            int X = r & 60;
            KP[(r + 0) * 64 + (n ^ X)] = kv.x;
            KP[(r + 1) * 64 + (n ^ X)] = kv.y;
            KP[(r + 2) * 64 + (n ^ X)] = kv.z;
            KP[(r + 3) * 64 + (n ^ X)] = kv.w;
            float4 vv = *(const float4*)(Vbase + (size_t)n * (NKV * HD) + dq * 4);
            *(float4*)&Vs[n * 64 + dq * 4] = vv;
        }
        __syncthreads();

        float s[8][8];
#pragma unroll
        for (int j = 0; j < 8; ++j)
#pragma unroll
            for (int i = 0; i < 8; ++i) s[j][i] = 0.0f;

#pragma unroll 4
        for (int d = 0; d < 64; ++d) {
            int X = d & 60;
            const float* qr = &Qt[d * 64];
            const float* kr = &KP[d * 64];
            int ca = (ty * 8) ^ X;
            int cb = (tx * 8) ^ X;
            float4 a0 = *(const float4*)(qr + ca);
            float4 a1 = *(const float4*)(qr + (ca ^ 4));
            float4 b0 = *(const float4*)(kr + cb);
            float4 b1 = *(const float4*)(kr + (cb ^ 4));
            float aa[8] = {a0.x, a0.y, a0.z, a0.w, a1.x, a1.y, a1.z, a1.w};
            float bb[8] = {b0.x, b0.y, b0.z, b0.w, b1.x, b1.y, b1.z, b1.w};
#pragma unroll
            for (int j = 0; j < 8; ++j)
#pragma unroll
                for (int i = 0; i < 8; ++i)
                    s[j][i] = fmaf(aa[i], bb[j], s[j][i]);
        }

        const bool diag = (jt == qt);
#pragma unroll
        for (int i = 0; i < 8; ++i) {
            float mloc = -1e30f;
#pragma unroll
            for (int j = 0; j < 8; ++j) {
                float v = s[j][i] * 0.125f;
                if (diag && (tx * 8 + j) > (ty * 8 + i)) v = -1e30f;
                s[j][i] = v;
                mloc = fmaxf(mloc, v);
            }
            mloc = fmaxf(mloc, __shfl_xor_sync(0xffffffffu, mloc, 4));
            mloc = fmaxf(mloc, __shfl_xor_sync(0xffffffffu, mloc, 2));
            mloc = fmaxf(mloc, __shfl_xor_sync(0xffffffffu, mloc, 1));
            float mnew = fmaxf(mi[i], mloc);
            float sf = __expf(mi[i] - mnew);
            float ps = 0.0f;
#pragma unroll
            for (int j = 0; j < 8; ++j) {
                float p = __expf(s[j][i] - mnew);
                s[j][i] = p;
                ps += p;
            }
            ps += __shfl_xor_sync(0xffffffffu, ps, 4);
            ps += __shfl_xor_sync(0xffffffffu, ps, 2);
            ps += __shfl_xor_sync(0xffffffffu, ps, 1);
            li[i] = li[i] * sf + ps;
            mi[i] = mnew;
#pragma unroll
            for (int dj = 0; dj < 8; ++dj) o[i][dj] *= sf;
        }

        __syncthreads();
#pragma unroll
        for (int j = 0; j < 8; ++j) {
            int n = tx * 8 + j;
            int X = n & 60;
            int c = (ty * 8) ^ X;
            *(float4*)&KP[n * 64 + c] =
                make_float4(s[j][0], s[j][1], s[j][2], s[j][3]);
            *(float4*)&KP[n * 64 + (c ^ 4)] =
                make_float4(s[j][4], s[j][5], s[j][6], s[j][7]);
        }
        __syncthreads();

#pragma unroll 4
        for (int n = 0; n < 64; ++n) {
            int X = n & 60;
            int ca = (ty * 8) ^ X;
            float4 p0 = *(const float4*)&KP[n * 64 + ca];
            float4 p1 = *(const float4*)&KP[n * 64 + (ca ^ 4)];
            float4 v0 = *(const float4*)&Vs[n * 64 + tx * 8];
            float4 v1 = *(const float4*)&Vs[n * 64 + tx * 8 + 4];
            float pp[8] = {p0.x, p0.y, p0.z, p0.w, p1.x, p1.y, p1.z, p1.w};
            float vv[8] = {v0.x, v0.y, v0.z, v0.w, v1.x, v1.y, v1.z, v1.w};
#pragma unroll
            for (int i = 0; i < 8; ++i)
#pragma unroll
                for (int dj = 0; dj < 8; ++dj)
                    o[i][dj] = fmaf(pp[i], vv[dj], o[i][dj]);
        }
    }

    float* Obase = O + ((size_t)((size_t)b * SEQ + q0) * NH + h) * HD;
#pragma unroll
    for (int i = 0; i < 8; ++i) {
        float inv = 1.0f / li[i];
        float* orow = Obase + (size_t)(ty * 8 + i) * (NH * HD) + tx * 8;
        *(float4*)orow = make_float4(o[i][0] * inv, o[i][1] * inv,
                                     o[i][2] * inv, o[i][3] * inv);
        *(float4*)(orow + 4) = make_float4(o[i][4] * inv, o[i][5] * inv,
                                           o[i][6] * inv, o[i][7] * inv);
    }
}

// ---------------------------------------------------------------------------
extern "C" void kernel_launch(void* const* d_in, const int* in_sizes, int n_in,
                              void* d_out, int out_size)
{
    const float* x  = (const float*)d_in[0];
    const float* Wq = (const float*)d_in[1];
    const float* Wk = (const float*)d_in[2];
    const float* Wv = (const float*)d_in[3];
    const float* Wo = (const float*)d_in[4];
    float* out = (float*)d_out;

    float *Q, *K, *V, *Oc;
    cudaGetSymbolAddress((void**)&Q,  g_Q);
    cudaGetSymbolAddress((void**)&K,  g_K);
    cudaGetSymbolAddress((void**)&V,  g_V);
    cudaGetSymbolAddress((void**)&Oc, g_O);
    __nv_bfloat16 *xhi, *xlo, *wqh, *wql, *wkh, *wkl, *wvh, *wvl, *woh, *wol;
    cudaGetSymbolAddress((void**)&xhi, g_xhi);
    cudaGetSymbolAddress((void**)&xlo, g_xlo);
    cudaGetSymbolAddress((void**)&wqh, g_wqt_hi);
    cudaGetSymbolAddress((void**)&wql, g_wqt_lo);
    cudaGetSymbolAddress((void**)&wkh, g_wkt_hi);
    cudaGetSymbolAddress((void**)&wkl, g_wkt_lo);
    cudaGetSymbolAddress((void**)&wvh, g_wvt_hi);
    cudaGetSymbolAddress((void**)&wvl, g_wvt_lo);
    cudaGetSymbolAddress((void**)&woh, g_wot_hi);
    cudaGetSymbolAddress((void**)&wol, g_wot_lo);

    cudaFuncSetAttribute(gemm_mma, cudaFuncAttributeMaxDynamicSharedMemorySize,
                         GEMM_SMEM);

    const int M = MTOT;           // 4096
    const int NKVD = NKV * HD;    // 512

    // Split x, transpose+split weights
    {
        int n = M * DMODEL;
        split_kernel<<<(n + 255) / 256, 256>>>(x, xhi, xlo, n);
        splitT_kernel<<<dim3(DMODEL / 32, DMODEL / 32), dim3(32, 8)>>>(Wq, wqh, wql, DMODEL, DMODEL);
        splitT_kernel<<<dim3(NKVD / 32,  DMODEL / 32), dim3(32, 8)>>>(Wk, wkh, wkl, DMODEL, NKVD);
        splitT_kernel<<<dim3(NKVD / 32,  DMODEL / 32), dim3(32, 8)>>>(Wv, wvh, wvl, DMODEL, NKVD);
        splitT_kernel<<<dim3(DMODEL / 32, DMODEL / 32), dim3(32, 8)>>>(Wo, woh, wol, DMODEL, DMODEL);
    }

    // QKV projections (tensor cores via mma.sync)
    gemm_mma<<<dim3(DMODEL / 128, M / 128), 256, GEMM_SMEM>>>(xhi, xlo, wqh, wql, Q, M, DMODEL, DMODEL);
    gemm_mma<<<dim3(NKVD / 128,  M / 128), 256, GEMM_SMEM>>>(xhi, xlo, wkh, wkl, K, M, NKVD, DMODEL);
    gemm_mma<<<dim3(NKVD / 128,  M / 128), 256, GEMM_SMEM>>>(xhi, xlo, wvh, wvl, V, M, NKVD, DMODEL);

    // RoPE
    {
        int totQ = MTOT * NH * (HD / 2);
        int totK = MTOT * NKV * (HD / 2);
        rope_kernel<<<(totQ + 255) / 256, 256>>>(Q, NH, totQ);
        rope_kernel<<<(totK + 255) / 256, 256>>>(K, NKV, totK);
    }

    // Attention
    attn_kernel<<<dim3(SEQ / 64, NH, BATCH), 64>>>(Q, K, V, Oc);

    // Output projection (split Oc, reuse x buffers)
    {
        int n = M * DMODEL;
        split_kernel<<<(n + 255) / 256, 256>>>(Oc, xhi, xlo, n);
        gemm_mma<<<dim3(DMODEL / 128, M / 128), 256, GEMM_SMEM>>>(xhi, xlo, woh, wol, out, M, DMODEL, DMODEL);
    }
}

// round 4
// speedup vs baseline: 2.3062x; 1.4651x over previous
#include <cuda_runtime.h>
#include <cuda_bf16.h>
#include <math.h>
#include <stdint.h>

#define BATCH 2
#define SEQ   2048
#define DMODEL 2048
#define NH    32
#define NKV   8
#define HD    64
#define MTOT  (BATCH * SEQ)          // 4096

// ---------------- scratch (device globals; no allocation allowed) ----------
__device__ float g_Q[MTOT * NH * HD];    // fp32 gemm outputs
__device__ float g_K[MTOT * NKV * HD];
__device__ float g_V[MTOT * NKV * HD];

__device__ __nv_bfloat16 g_xhi[MTOT * DMODEL];
__device__ __nv_bfloat16 g_xlo[MTOT * DMODEL];
__device__ __nv_bfloat16 g_wqt_hi[DMODEL * DMODEL];
__device__ __nv_bfloat16 g_wqt_lo[DMODEL * DMODEL];
__device__ __nv_bfloat16 g_wkt_hi[(NKV * HD) * DMODEL];
__device__ __nv_bfloat16 g_wkt_lo[(NKV * HD) * DMODEL];
__device__ __nv_bfloat16 g_wvt_hi[(NKV * HD) * DMODEL];
__device__ __nv_bfloat16 g_wvt_lo[(NKV * HD) * DMODEL];
__device__ __nv_bfloat16 g_wot_hi[DMODEL * DMODEL];
__device__ __nv_bfloat16 g_wot_lo[DMODEL * DMODEL];

// bf16 hi/lo attention operands
__device__ __nv_bfloat16 g_Qh[MTOT * NH * HD];
__device__ __nv_bfloat16 g_Ql[MTOT * NH * HD];
__device__ __nv_bfloat16 g_Kh[MTOT * NKV * HD];
__device__ __nv_bfloat16 g_Kl[MTOT * NKV * HD];
__device__ __nv_bfloat16 g_Vh[MTOT * NKV * HD];
__device__ __nv_bfloat16 g_Vl[MTOT * NKV * HD];

// ---------------- PTX helpers ----------------------------------------------
__device__ __forceinline__ uint32_t smem_u32(const void* p) {
    uint32_t a;
    asm("{ .reg .u64 t; cvta.to.shared.u64 t, %1; cvt.u32.u64 %0, t; }"
        : "=r"(a) : "l"(p));
    return a;
}
__device__ __forceinline__ void cp_async16(uint32_t saddr, const void* gaddr) {
    asm volatile("cp.async.cg.shared.global [%0], [%1], 16;"
                 :: "r"(saddr), "l"(gaddr) : "memory");
}
__device__ __forceinline__ void cp_commit() {
    asm volatile("cp.async.commit_group;" ::: "memory");
}
template <int N>
__device__ __forceinline__ void cp_wait() {
    asm volatile("cp.async.wait_group %0;" :: "n"(N) : "memory");
}
__device__ __forceinline__ void ldsm_x4(uint32_t& r0, uint32_t& r1, uint32_t& r2,
                                        uint32_t& r3, uint32_t addr) {
    asm volatile("ldmatrix.sync.aligned.m8n8.x4.shared.b16 {%0,%1,%2,%3}, [%4];"
                 : "=r"(r0), "=r"(r1), "=r"(r2), "=r"(r3) : "r"(addr));
}
__device__ __forceinline__ void ldsm_x4_t(uint32_t& r0, uint32_t& r1, uint32_t& r2,
                                          uint32_t& r3, uint32_t addr) {
    asm volatile("ldmatrix.sync.aligned.m8n8.x4.trans.shared.b16 {%0,%1,%2,%3}, [%4];"
                 : "=r"(r0), "=r"(r1), "=r"(r2), "=r"(r3) : "r"(addr));
}
__device__ __forceinline__ void ldsm_x2(uint32_t& r0, uint32_t& r1, uint32_t addr) {
    asm volatile("ldmatrix.sync.aligned.m8n8.x2.shared.b16 {%0,%1}, [%2];"
                 : "=r"(r0), "=r"(r1) : "r"(addr));
}
__device__ __forceinline__ void mma_bf16(float* c, const uint32_t* a, const uint32_t* b) {
    asm volatile(
        "mma.sync.aligned.m16n8k16.row.col.f32.bf16.bf16.f32 "
        "{%0,%1,%2,%3}, {%4,%5,%6,%7}, {%8,%9}, {%0,%1,%2,%3};"
        : "+f"(c[0]), "+f"(c[1]), "+f"(c[2]), "+f"(c[3])
        : "r"(a[0]), "r"(a[1]), "r"(a[2]), "r"(a[3]), "r"(b[0]), "r"(b[1]));
}
__device__ __forceinline__ uint32_t pack_bf16(float lo, float hi) {
    __nv_bfloat162 t = __floats2bfloat162_rn(lo, hi);
    return *(uint32_t*)&t;
}

// ---------------------------------------------------------------------------
// Split fp32 -> bf16 hi/lo (elementwise)
// ---------------------------------------------------------------------------
__global__ void split_kernel(const float* __restrict__ X,
                             __nv_bfloat16* __restrict__ hi,
                             __nv_bfloat16* __restrict__ lo, int n)
{
    int i = blockIdx.x * blockDim.x + threadIdx.x;
    if (i >= n) return;
    float x = X[i];
    __nv_bfloat16 h = __float2bfloat16(x);
    hi[i] = h;
    lo[i] = __float2bfloat16(x - __bfloat162float(h));
}

// ---------------------------------------------------------------------------
// Transpose + split: W[K,N] fp32 -> Th,Tl [N,K] bf16
// ---------------------------------------------------------------------------
__global__ void splitT_kernel(const float* __restrict__ W,
                              __nv_bfloat16* __restrict__ Th,
                              __nv_bfloat16* __restrict__ Tl, int Kd, int Nd)
{
    __shared__ float t[32][33];
    int k0 = blockIdx.y * 32, n0 = blockIdx.x * 32;
    int tx = threadIdx.x, ty = threadIdx.y;  // 32 x 8
#pragma unroll
    for (int r = ty; r < 32; r += 8)
        t[r][tx] = W[(size_t)(k0 + r) * Nd + n0 + tx];
    __syncthreads();
#pragma unroll
    for (int r = ty; r < 32; r += 8) {
        float x = t[tx][r];
        __nv_bfloat16 h = __float2bfloat16(x);
        size_t o = (size_t)(n0 + r) * Kd + k0 + tx;
        Th[o] = h;
        Tl[o] = __float2bfloat16(x - __bfloat162float(h));
    }
}

// ---------------------------------------------------------------------------
// RoPE + scale + split: fp32 [B,S,nh,HD] -> bf16 hi/lo with rotation applied
// ---------------------------------------------------------------------------
__global__ void rope_split_kernel(const float* __restrict__ T,
                                  __nv_bfloat16* __restrict__ Th,
                                  __nv_bfloat16* __restrict__ Tl,
                                  int nheads, float scale, int total)
{
    int idx = blockIdx.x * blockDim.x + threadIdx.x;
    if (idx >= total) return;
    int d = idx & 31;
    int t = idx >> 5;
    int s = (t / nheads) % SEQ;

    float invf = 1.0f / powf(10000.0f, (float)d * (1.0f / 32.0f));
    float ang = (float)s * invf;
    float sn, cs;
    sincosf(ang, &sn, &cs);

    const float* p = T + (size_t)t * HD + d;
    float x0 = p[0];
    float x1 = p[32];
    float y0 = (x0 * cs - x1 * sn) * scale;
    float y1 = (x1 * cs + x0 * sn) * scale;

    size_t o = (size_t)t * HD + d;
    __nv_bfloat16 h0 = __float2bfloat16(y0);
    __nv_bfloat16 h1 = __float2bfloat16(y1);
    Th[o] = h0;      Tl[o] = __float2bfloat16(y0 - __bfloat162float(h0));
    Th[o + 32] = h1; Tl[o + 32] = __float2bfloat16(y1 - __bfloat162float(h1));
}

// ---------------------------------------------------------------------------
// mma.sync bf16x3 GEMM (unchanged from R3, passing)
// ---------------------------------------------------------------------------
#define BK     32
#define PITCH  80
#define TILE_B (128 * PITCH)
#define STAGE_B (4 * TILE_B)
#define GEMM_SMEM (2 * STAGE_B)

__global__ __launch_bounds__(256, 1)
void gemm_mma(const __nv_bfloat16* __restrict__ Ah, const __nv_bfloat16* __restrict__ Al,
              const __nv_bfloat16* __restrict__ Bh, const __nv_bfloat16* __restrict__ Bl,
              float* __restrict__ C, int M, int N, int K)
{
    extern __shared__ char sm[];
    const int tid  = threadIdx.x;
    const int lane = tid & 31;
    const int wid  = tid >> 5;
    const int wm   = wid & 1;
    const int wn   = wid >> 1;
    const int m0 = blockIdx.y * 128;
    const int n0 = blockIdx.x * 128;

    const __nv_bfloat16* srcs[4] = {Ah, Al, Bh, Bl};
    const int r0s[4] = {m0, m0, n0, n0};

    float acc[4][4][4];
#pragma unroll
    for (int i = 0; i < 4; ++i)
#pragma unroll
        for (int j = 0; j < 4; ++j)
#pragma unroll
            for (int q = 0; q < 4; ++q) acc[i][j][q] = 0.0f;

    const int nc = K / BK;

    {
        char* st = sm;
#pragma unroll
        for (int t = 0; t < 4; ++t) {
            const __nv_bfloat16* src = srcs[t];
            const int r0 = r0s[t];
            char* dst = st + t * TILE_B;
#pragma unroll
            for (int u = 0; u < 2; ++u) {
                int v = tid + u * 256;
                int row = v >> 2, q = v & 3;
                cp_async16(smem_u32(dst + row * PITCH + q * 16),
                           src + (size_t)(r0 + row) * K + q * 8);
            }
        }
        cp_commit();
    }

    for (int c = 0; c < nc; ++c) {
        if (c + 1 < nc) {
            char* st = sm + ((c + 1) & 1) * STAGE_B;
            const int k0 = (c + 1) * BK;
#pragma unroll
            for (int t = 0; t < 4; ++t) {
                const __nv_bfloat16* src = srcs[t];
                const int r0 = r0s[t];
                char* dst = st + t * TILE_B;
#pragma unroll
                for (int u = 0; u < 2; ++u) {
                    int v = tid + u * 256;
                    int row = v >> 2, q = v & 3;
                    cp_async16(smem_u32(dst + row * PITCH + q * 16),
                               src + (size_t)(r0 + row) * K + k0 + q * 8);
                }
            }
            cp_commit();
            cp_wait<1>();
        } else {
            cp_wait<0>();
        }
        __syncthreads();

        char* st = sm + (c & 1) * STAGE_B;
        char* sAh = st;
        char* sAl = st + TILE_B;
        char* sBh = st + 2 * TILE_B;
        char* sBl = st + 3 * TILE_B;

#pragma unroll
        for (int ks = 0; ks < 2; ++ks) {
            uint32_t ah[4][4], al[4][4];
            const int arow = wm * 64 + (lane & 15);
            const int achk = ks * 2 + (lane >> 4);
#pragma unroll
            for (int i = 0; i < 4; ++i) {
                uint32_t off = (uint32_t)((arow + i * 16) * PITCH + achk * 16);
                ldsm_x4(ah[i][0], ah[i][1], ah[i][2], ah[i][3], smem_u32(sAh + off));
                ldsm_x4(al[i][0], al[i][1], al[i][2], al[i][3], smem_u32(sAl + off));
            }
            uint32_t bh[4][2], bl[4][2];
            const int brow = wn * 32 + (lane & 7);
            const int bchk = ks * 2 + ((lane >> 3) & 1);
#pragma unroll
            for (int j = 0; j < 4; ++j) {
                uint32_t off = (uint32_t)((brow + j * 8) * PITCH + bchk * 16);
                ldsm_x2(bh[j][0], bh[j][1], smem_u32(sBh + off));
                ldsm_x2(bl[j][0], bl[j][1], smem_u32(sBl + off));
            }
#pragma unroll
            for (int i = 0; i < 4; ++i)
#pragma unroll
                for (int j = 0; j < 4; ++j) {
                    mma_bf16(acc[i][j], ah[i], bh[j]);
                    mma_bf16(acc[i][j], ah[i], bl[j]);
                    mma_bf16(acc[i][j], al[i], bh[j]);
                }
        }
        __syncthreads();
    }

#pragma unroll
    for (int i = 0; i < 4; ++i) {
        int row = m0 + wm * 64 + i * 16 + (lane >> 2);
#pragma unroll
        for (int j = 0; j < 4; ++j) {
            int col = n0 + wn * 32 + j * 8 + (lane & 3) * 2;
            *(float2*)(C + (size_t)row * N + col) =
                make_float2(acc[i][j][0], acc[i][j][1]);
            *(float2*)(C + (size_t)(row + 8) * N + col) =
                make_float2(acc[i][j][2], acc[i][j][3]);
        }
    }
}

// ---------------------------------------------------------------------------
// mma.sync causal flash attention, GQA. 128 threads (4 warps).
// CTA: 64 query rows of one (b,h). Warp w owns rows 16w..16w+15.
// K/V bf16 hi/lo tiles stream via 2-stage cp.async. Softmax in fragment regs.
// ---------------------------------------------------------------------------
#define AP 144                           // smem row pitch (64 bf16 + pad)
#define ATILE (64 * AP)                  // 9216 B per tile
#define ASTAGE (4 * ATILE)               // Kh,Kl,Vh,Vl
#define AQ_B  (2 * ATILE)                // Qh,Ql
#define ATTN_SMEM (AQ_B + 2 * ASTAGE)    // 92160 B

__global__ __launch_bounds__(128)
void attn_mma(const __nv_bfloat16* __restrict__ Qh_g, const __nv_bfloat16* __restrict__ Ql_g,
              const __nv_bfloat16* __restrict__ Kh_g, const __nv_bfloat16* __restrict__ Kl_g,
              const __nv_bfloat16* __restrict__ Vh_g, const __nv_bfloat16* __restrict__ Vl_g,
              __nv_bfloat16* __restrict__ Oh_g, __nv_bfloat16* __restrict__ Ol_g)
{
    extern __shared__ char sm[];
    char* sQ  = sm;                     // Qh, Ql

    const int tid  = threadIdx.x;
    const int lane = tid & 31;
    const int w    = tid >> 5;          // warp 0..3
    const int qt   = blockIdx.x;        // q block
    const int h    = blockIdx.y;
    const int b    = blockIdx.z;
    const int g    = h >> 2;
    const int q0   = qt * 64;

    const int lam = lane & 3;           // quad col (2*lam, 2*lam+1)
    const int rho = lane >> 2;          // quad row

    // ---- prologue: load Q (hi/lo) + stage 0 of K/V ----
    {
        const __nv_bfloat16* qs[2] = {Qh_g, Ql_g};
#pragma unroll
        for (int u = 0; u < 8; ++u) {
            int idx = tid + u * 128;            // 0..1023
            int t = idx >> 9, rem = idx & 511;
            int row = rem >> 3, c = rem & 7;
            cp_async16(smem_u32(sQ + t * ATILE + row * AP + c * 16),
                       qs[t] + ((size_t)(b * SEQ + q0 + row) * NH + h) * HD + c * 8);
        }
        const __nv_bfloat16* ks[4] = {Kh_g, Kl_g, Vh_g, Vl_g};
        char* stg = sm + AQ_B;
#pragma unroll
        for (int u = 0; u < 16; ++u) {
            int idx = tid + u * 128;            // 0..2047
            int t = idx >> 9, rem = idx & 511;
            int row = rem >> 3, c = rem & 7;
            cp_async16(smem_u32(stg + t * ATILE + row * AP + c * 16),
                       ks[t] + ((size_t)(b * SEQ + row) * NKV + g) * HD + c * 8);
        }
        cp_commit();
    }

    uint32_t qh[4][4], ql[4][4];        // A-fragments, loaded once at jt==0
    float m[2] = {-1e30f, -1e30f};
    float l[2] = {0.0f, 0.0f};
    float o[8][4];
#pragma unroll
    for (int j = 0; j < 8; ++j)
#pragma unroll
        for (int e = 0; e < 4; ++e) o[j][e] = 0.0f;

    for (int jt = 0; jt <= qt; ++jt) {
        // prefetch next K/V stage
        if (jt < qt) {
            const __nv_bfloat16* ks[4] = {Kh_g, Kl_g, Vh_g, Vl_g};
            char* stg = sm + AQ_B + ((jt + 1) & 1) * ASTAGE;
            const int n0 = (jt + 1) * 64;
#pragma unroll
            for (int u = 0; u < 16; ++u) {
                int idx = tid + u * 128;
                int t = idx >> 9, rem = idx & 511;
                int row = rem >> 3, c = rem & 7;
                cp_async16(smem_u32(stg + t * ATILE + row * AP + c * 16),
                           ks[t] + ((size_t)(b * SEQ + n0 + row) * NKV + g) * HD + c * 8);
            }
            cp_commit();
            cp_wait<1>();
        } else {
            cp_wait<0>();
        }
        __syncthreads();

        if (jt == 0) {
            // load Q fragments (persist across iterations)
#pragma unroll
            for (int kk = 0; kk < 4; ++kk) {
                uint32_t off = (uint32_t)((16 * w + (lane & 15)) * AP +
                                          kk * 32 + (lane >> 4) * 16);
                ldsm_x4(qh[kk][0], qh[kk][1], qh[kk][2], qh[kk][3],
                        smem_u32(sQ + off));
                ldsm_x4(ql[kk][0], ql[kk][1], ql[kk][2], ql[kk][3],
                        smem_u32(sQ + ATILE + off));
            }
        }

        char* stg = sm + AQ_B + (jt & 1) * ASTAGE;
        char* sKh = stg;
        char* sKl = stg + ATILE;
        char* sVh = stg + 2 * ATILE;
        char* sVl = stg + 3 * ATILE;

        // ---- S = Q K^T (split-3) ----
        float s[8][4];
#pragma unroll
        for (int j = 0; j < 8; ++j) {
            s[j][0] = s[j][1] = s[j][2] = s[j][3] = 0.0f;
            uint32_t boff = (uint32_t)((8 * j + (lane & 7)) * AP +
                                       ((lane >> 3) & 3) * 16);
            uint32_t kh[8], kl[8];
            ldsm_x4(kh[0], kh[1], kh[2], kh[3], smem_u32(sKh + boff));
            ldsm_x4(kh[4], kh[5], kh[6], kh[7], smem_u32(sKh + boff + 64));
            ldsm_x4(kl[0], kl[1], kl[2], kl[3], smem_u32(sKl + boff));
            ldsm_x4(kl[4], kl[5], kl[6], kl[7], smem_u32(sKl + boff + 64));
#pragma unroll
            for (int kk = 0; kk < 4; ++kk) {
                mma_bf16(s[j], qh[kk], &kh[kk * 2]);
                mma_bf16(s[j], qh[kk], &kl[kk * 2]);
                mma_bf16(s[j], ql[kk], &kh[kk * 2]);
            }
        }

        // ---- mask + online softmax (fragment layout) ----
        if (jt == qt) {
            const int r0 = 16 * w + rho;
#pragma unroll
            for (int j = 0; j < 8; ++j) {
                int c0 = 8 * j + 2 * lam;
                if (c0 > r0)     s[j][0] = -1e30f;
                if (c0 + 1 > r0) s[j][1] = -1e30f;
                if (c0 > r0 + 8)     s[j][2] = -1e30f;
                if (c0 + 1 > r0 + 8) s[j][3] = -1e30f;
            }
        }
#pragma unroll
        for (int r = 0; r < 2; ++r) {
            float loc = -1e30f;
#pragma unroll
            for (int j = 0; j < 8; ++j)
                loc = fmaxf(loc, fmaxf(s[j][r * 2], s[j][r * 2 + 1]));
            loc = fmaxf(loc, __shfl_xor_sync(0xffffffffu, loc, 1));
            loc = fmaxf(loc, __shfl_xor_sync(0xffffffffu, loc, 2));
            float mnew = fmaxf(m[r], loc);
            float sf = __expf(m[r] - mnew);
            float ps = 0.0f;
#pragma unroll
            for (int j = 0; j < 8; ++j) {
                float p0 = __expf(s[j][r * 2]     - mnew);
                float p1 = __expf(s[j][r * 2 + 1] - mnew);
                s[j][r * 2] = p0; s[j][r * 2 + 1] = p1;
                ps += p0 + p1;
            }
            ps += __shfl_xor_sync(0xffffffffu, ps, 1);
            ps += __shfl_xor_sync(0xffffffffu, ps, 2);
            l[r] = l[r] * sf + ps;
            m[r] = mnew;
#pragma unroll
            for (int j = 0; j < 8; ++j) {
                o[j][r * 2]     *= sf;
                o[j][r * 2 + 1] *= sf;
            }
        }

        // ---- P fragments (hi/lo split, in registers) ----
        uint32_t ph[4][4], pl[4][4];
#pragma unroll
        for (int kk = 0; kk < 4; ++kk) {
            float* t0 = s[2 * kk];
            float* t1 = s[2 * kk + 1];
            float e[8] = {t0[0], t0[1], t0[2], t0[3], t1[0], t1[1], t1[2], t1[3]};
            float hi[8], lo[8];
#pragma unroll
            for (int q = 0; q < 8; ++q) {
                __nv_bfloat16 hb = __float2bfloat16(e[q]);
                hi[q] = __bfloat162float(hb);
                lo[q] = e[q] - hi[q];
            }
            ph[kk][0] = pack_bf16(hi[0], hi[1]);
            ph[kk][1] = pack_bf16(hi[2], hi[3]);
            ph[kk][2] = pack_bf16(hi[4], hi[5]);
            ph[kk][3] = pack_bf16(hi[6], hi[7]);
            pl[kk][0] = pack_bf16(lo[0], lo[1]);
            pl[kk][1] = pack_bf16(lo[2], lo[3]);
            pl[kk][2] = pack_bf16(lo[4], lo[5]);
            pl[kk][3] = pack_bf16(lo[6], lo[7]);
        }

        // ---- O += P V (split-3) ----
#pragma unroll
        for (int p2 = 0; p2 < 4; ++p2) {
#pragma unroll
            for (int kk = 0; kk < 4; ++kk) {
                uint32_t voff = (uint32_t)((16 * kk + (lane & 15)) * AP +
                                           (2 * p2 + (lane >> 4)) * 16);
                uint32_t vh[4], vl[4];
                ldsm_x4_t(vh[0], vh[1], vh[2], vh[3], smem_u32(sVh + voff));
                ldsm_x4_t(vl[0], vl[1], vl[2], vl[3], smem_u32(sVl + voff));
                mma_bf16(o[2 * p2],     ph[kk], &vh[0]);
                mma_bf16(o[2 * p2],     ph[kk], &vl[0]);
                mma_bf16(o[2 * p2],     pl[kk], &vh[0]);
                mma_bf16(o[2 * p2 + 1], ph[kk], &vh[2]);
                mma_bf16(o[2 * p2 + 1], ph[kk], &vl[2]);
                mma_bf16(o[2 * p2 + 1], pl[kk], &vh[2]);
            }
        }
        __syncthreads();
    }

    // ---- epilogue: normalize, split hi/lo, store bf16 ----
    float inv0 = 1.0f / l[0];
    float inv1 = 1.0f / l[1];
    const int row0 = q0 + 16 * w + rho;
#pragma unroll
    for (int j = 0; j < 8; ++j) {
        int col = 8 * j + 2 * lam;
        size_t o0 = ((size_t)(b * SEQ + row0) * NH + h) * HD + col;
        size_t o1 = ((size_t)(b * SEQ + row0 + 8) * NH + h) * HD + col;
        float v00 = o[j][0] * inv0, v01 = o[j][1] * inv0;
        float v10 = o[j][2] * inv1, v11 = o[j][3] * inv1;
        float h00 = __bfloat162float(__float2bfloat16(v00));
        float h01 = __bfloat162float(__float2bfloat16(v01));
        float h10 = __bfloat162float(__float2bfloat16(v10));
        float h11 = __bfloat162float(__float2bfloat16(v11));
        *(uint32_t*)(Oh_g + o0) = pack_bf16(h00, h01);
        *(uint32_t*)(Ol_g + o0) = pack_bf16(v00 - h00, v01 - h01);
        *(uint32_t*)(Oh_g + o1) = pack_bf16(h10, h11);
        *(uint32_t*)(Ol_g + o1) = pack_bf16(v10 - h10, v11 - h11);
    }
}

// ---------------------------------------------------------------------------
extern "C" void kernel_launch(void* const* d_in, const int* in_sizes, int n_in,
                              void* d_out, int out_size)
{
    const float* x  = (const float*)d_in[0];
    const float* Wq = (const float*)d_in[1];
    const float* Wk = (const float*)d_in[2];
    const float* Wv = (const float*)d_in[3];
    const float* Wo = (const float*)d_in[4];
    float* out = (float*)d_out;

    float *Q, *K, *V;
    cudaGetSymbolAddress((void**)&Q, g_Q);
    cudaGetSymbolAddress((void**)&K, g_K);
    cudaGetSymbolAddress((void**)&V, g_V);
    __nv_bfloat16 *xhi, *xlo, *wqh, *wql, *wkh, *wkl, *wvh, *wvl, *woh, *wol;
    __nv_bfloat16 *qh, *ql, *kh, *kl, *vh, *vl;
    cudaGetSymbolAddress((void**)&xhi, g_xhi);
    cudaGetSymbolAddress((void**)&xlo, g_xlo);
    cudaGetSymbolAddress((void**)&wqh, g_wqt_hi);
    cudaGetSymbolAddress((void**)&wql, g_wqt_lo);
    cudaGetSymbolAddress((void**)&wkh, g_wkt_hi);
    cudaGetSymbolAddress((void**)&wkl, g_wkt_lo);
    cudaGetSymbolAddress((void**)&wvh, g_wvt_hi);
    cudaGetSymbolAddress((void**)&wvl, g_wvt_lo);
    cudaGetSymbolAddress((void**)&woh, g_wot_hi);
    cudaGetSymbolAddress((void**)&wol, g_wot_lo);
    cudaGetSymbolAddress((void**)&qh, g_Qh);
    cudaGetSymbolAddress((void**)&ql, g_Ql);
    cudaGetSymbolAddress((void**)&kh, g_Kh);
    cudaGetSymbolAddress((void**)&kl, g_Kl);
    cudaGetSymbolAddress((void**)&vh, g_Vh);
    cudaGetSymbolAddress((void**)&vl, g_Vl);

    cudaFuncSetAttribute(gemm_mma, cudaFuncAttributeMaxDynamicSharedMemorySize,
                         GEMM_SMEM);
    cudaFuncSetAttribute(attn_mma, cudaFuncAttributeMaxDynamicSharedMemorySize,
                         ATTN_SMEM);

    const int M = MTOT;           // 4096
    const int NKVD = NKV * HD;    // 512

    // Split x, transpose+split weights
    {
        int n = M * DMODEL;
        split_kernel<<<(n + 255) / 256, 256>>>(x, xhi, xlo, n);
        splitT_kernel<<<dim3(DMODEL / 32, DMODEL / 32), dim3(32, 8)>>>(Wq, wqh, wql, DMODEL, DMODEL);
        splitT_kernel<<<dim3(NKVD / 32,  DMODEL / 32), dim3(32, 8)>>>(Wk, wkh, wkl, DMODEL, NKVD);
        splitT_kernel<<<dim3(NKVD / 32,  DMODEL / 32), dim3(32, 8)>>>(Wv, wvh, wvl, DMODEL, NKVD);
        splitT_kernel<<<dim3(DMODEL / 32, DMODEL / 32), dim3(32, 8)>>>(Wo, woh, wol, DMODEL, DMODEL);
    }

    // QKV projections
    gemm_mma<<<dim3(DMODEL / 128, M / 128), 256, GEMM_SMEM>>>(xhi, xlo, wqh, wql, Q, M, DMODEL, DMODEL);
    gemm_mma<<<dim3(NKVD / 128,  M / 128), 256, GEMM_SMEM>>>(xhi, xlo, wkh, wkl, K, M, NKVD, DMODEL);
    gemm_mma<<<dim3(NKVD / 128,  M / 128), 256, GEMM_SMEM>>>(xhi, xlo, wvh, wvl, V, M, NKVD, DMODEL);

    // RoPE + scale + split (Q scaled by 1/sqrt(HD)); V plain split
    {
        int totQ = MTOT * NH * 32;
        int totK = MTOT * NKV * 32;
        rope_split_kernel<<<(totQ + 255) / 256, 256>>>(Q, qh, ql, NH, 0.125f, totQ);
        rope_split_kernel<<<(totK + 255) / 256, 256>>>(K, kh, kl, NKV, 1.0f, totK);
        int nV = MTOT * NKVD;
        split_kernel<<<(nV + 255) / 256, 256>>>(V, vh, vl, nV);
    }

    // Attention (tensor cores); writes hi/lo split of O into xhi/xlo
    attn_mma<<<dim3(SEQ / 64, NH, BATCH), 128, ATTN_SMEM>>>(qh, ql, kh, kl, vh, vl, xhi, xlo);

    // Output projection
    gemm_mma<<<dim3(DMODEL / 128, M / 128), 256, GEMM_SMEM>>>(xhi, xlo, woh, wol, out, M, DMODEL, DMODEL);
}

// round 5
// speedup vs baseline: 3.1326x; 1.3583x over previous
#include <cuda_runtime.h>
#include <cuda_fp16.h>
#include <math.h>
#include <stdint.h>

#define BATCH 2
#define SEQ   2048
#define DMODEL 2048
#define NH    32
#define NKV   8
#define HD    64
#define MTOT  (BATCH * SEQ)          // 4096

// ---------------- scratch (device globals; no allocation allowed) ----------
__device__ float g_Q[MTOT * NH * HD];    // fp32 gemm outputs
__device__ float g_K[MTOT * NKV * HD];
__device__ float g_V[MTOT * NKV * HD];

__device__ __half g_xh[MTOT * DMODEL];       // A-side hi/lo (x, then O)
__device__ __half g_xl[MTOT * DMODEL];
__device__ __half g_wqt[DMODEL * DMODEL];    // weights: single fp16, [N,K]
__device__ __half g_wkt[(NKV * HD) * DMODEL];
__device__ __half g_wvt[(NKV * HD) * DMODEL];
__device__ __half g_wot[DMODEL * DMODEL];

__device__ __half g_Qh[MTOT * NH * HD];      // Q split hi/lo (A side of S)
__device__ __half g_Ql[MTOT * NH * HD];
__device__ __half g_Kh[MTOT * NKV * HD];     // K single fp16 (B side)
__device__ __half g_Vh[MTOT * NKV * HD];     // V single fp16 (B side)

// ---------------- PTX helpers ----------------------------------------------
__device__ __forceinline__ uint32_t smem_u32(const void* p) {
    uint32_t a;
    asm("{ .reg .u64 t; cvta.to.shared.u64 t, %1; cvt.u32.u64 %0, t; }"
        : "=r"(a) : "l"(p));
    return a;
}
__device__ __forceinline__ void cp_async16(uint32_t saddr, const void* gaddr) {
    asm volatile("cp.async.cg.shared.global [%0], [%1], 16;"
                 :: "r"(saddr), "l"(gaddr) : "memory");
}
__device__ __forceinline__ void cp_commit() {
    asm volatile("cp.async.commit_group;" ::: "memory");
}
template <int N>
__device__ __forceinline__ void cp_wait() {
    asm volatile("cp.async.wait_group %0;" :: "n"(N) : "memory");
}
__device__ __forceinline__ void ldsm_x4(uint32_t& r0, uint32_t& r1, uint32_t& r2,
                                        uint32_t& r3, uint32_t addr) {
    asm volatile("ldmatrix.sync.aligned.m8n8.x4.shared.b16 {%0,%1,%2,%3}, [%4];"
                 : "=r"(r0), "=r"(r1), "=r"(r2), "=r"(r3) : "r"(addr));
}
__device__ __forceinline__ void ldsm_x4_t(uint32_t& r0, uint32_t& r1, uint32_t& r2,
                                          uint32_t& r3, uint32_t addr) {
    asm volatile("ldmatrix.sync.aligned.m8n8.x4.trans.shared.b16 {%0,%1,%2,%3}, [%4];"
                 : "=r"(r0), "=r"(r1), "=r"(r2), "=r"(r3) : "r"(addr));
}
__device__ __forceinline__ void ldsm_x2(uint32_t& r0, uint32_t& r1, uint32_t addr) {
    asm volatile("ldmatrix.sync.aligned.m8n8.x2.shared.b16 {%0,%1}, [%2];"
                 : "=r"(r0), "=r"(r1) : "r"(addr));
}
__device__ __forceinline__ void mma_f16(float* c, const uint32_t* a, const uint32_t* b) {
    asm volatile(
        "mma.sync.aligned.m16n8k16.row.col.f32.f16.f16.f32 "
        "{%0,%1,%2,%3}, {%4,%5,%6,%7}, {%8,%9}, {%0,%1,%2,%3};"
        : "+f"(c[0]), "+f"(c[1]), "+f"(c[2]), "+f"(c[3])
        : "r"(a[0]), "r"(a[1]), "r"(a[2]), "r"(a[3]), "r"(b[0]), "r"(b[1]));
}
__device__ __forceinline__ uint32_t pack_h2(float a, float b) {
    __half2 t = __floats2half2_rn(a, b);
    return *(uint32_t*)&t;
}

// ---------------------------------------------------------------------------
// fp32 -> fp16 hi/lo split (elementwise)
// ---------------------------------------------------------------------------
__global__ void split2h_kernel(const float* __restrict__ X,
                               __half* __restrict__ hi,
                               __half* __restrict__ lo, int n)
{
    int i = blockIdx.x * blockDim.x + threadIdx.x;
    if (i >= n) return;
    float x = X[i];
    __half h = __float2half_rn(x);
    hi[i] = h;
    lo[i] = __float2half_rn(x - __half2float(h));
}

// fp32 -> fp16 (single)
__global__ void convh_kernel(const float* __restrict__ X,
                             __half* __restrict__ Y, int n)
{
    int i = blockIdx.x * blockDim.x + threadIdx.x;
    if (i >= n) return;
    Y[i] = __float2half_rn(X[i]);
}

// ---------------------------------------------------------------------------
// Transpose + convert: W[K,N] fp32 -> T [N,K] fp16 (single)
// ---------------------------------------------------------------------------
__global__ void transh_kernel(const float* __restrict__ W,
                              __half* __restrict__ T, int Kd, int Nd)
{
    __shared__ float t[32][33];
    int k0 = blockIdx.y * 32, n0 = blockIdx.x * 32;
    int tx = threadIdx.x, ty = threadIdx.y;  // 32 x 8
#pragma unroll
    for (int r = ty; r < 32; r += 8)
        t[r][tx] = W[(size_t)(k0 + r) * Nd + n0 + tx];
    __syncthreads();
#pragma unroll
    for (int r = ty; r < 32; r += 8)
        T[(size_t)(n0 + r) * Kd + k0 + tx] = __float2half_rn(t[tx][r]);
}

// ---------------------------------------------------------------------------
// RoPE + scale + fp16 hi/lo split (Q side)
// ---------------------------------------------------------------------------
__global__ void rope_split_h(const float* __restrict__ T,
                             __half* __restrict__ Th, __half* __restrict__ Tl,
                             int nheads, float scale, int total)
{
    int idx = blockIdx.x * blockDim.x + threadIdx.x;
    if (idx >= total) return;
    int d = idx & 31;
    int t = idx >> 5;
    int s = (t / nheads) % SEQ;

    float invf = 1.0f / powf(10000.0f, (float)d * (1.0f / 32.0f));
    float ang = (float)s * invf;
    float sn, cs;
    sincosf(ang, &sn, &cs);

    const float* p = T + (size_t)t * HD + d;
    float x0 = p[0];
    float x1 = p[32];
    float y0 = (x0 * cs - x1 * sn) * scale;
    float y1 = (x1 * cs + x0 * sn) * scale;

    size_t o = (size_t)t * HD + d;
    __half h0 = __float2half_rn(y0);
    __half h1 = __float2half_rn(y1);
    Th[o] = h0;      Tl[o] = __float2half_rn(y0 - __half2float(h0));
    Th[o + 32] = h1; Tl[o + 32] = __float2half_rn(y1 - __half2float(h1));
}

// RoPE + fp16 convert (K side, single)
__global__ void rope_h(const float* __restrict__ T, __half* __restrict__ Th,
                       int nheads, int total)
{
    int idx = blockIdx.x * blockDim.x + threadIdx.x;
    if (idx >= total) return;
    int d = idx & 31;
    int t = idx >> 5;
    int s = (t / nheads) % SEQ;

    float invf = 1.0f / powf(10000.0f, (float)d * (1.0f / 32.0f));
    float ang = (float)s * invf;
    float sn, cs;
    sincosf(ang, &sn, &cs);

    const float* p = T + (size_t)t * HD + d;
    float x0 = p[0];
    float x1 = p[32];
    size_t o = (size_t)t * HD + d;
    Th[o]      = __float2half_rn(x0 * cs - x1 * sn);
    Th[o + 32] = __float2half_rn(x1 * cs + x0 * sn);
}

// ---------------------------------------------------------------------------
// fp16 split-2 GEMM: C[M,N] = (Ah+Al)[M,K] @ Bh[N,K]^T, fp32 accum.
// CTA 128x128x32, 8 warps (2Mx4N). 3 tiles/stage (Ah, Al, Bh), 2 stages.
// ---------------------------------------------------------------------------
#define BK     32
#define PITCH  80
#define TILE_B (128 * PITCH)             // 10240 B
#define STAGE_B (3 * TILE_B)             // Ah, Al, Bh
#define GEMM_SMEM (2 * STAGE_B)          // 61440 B

__global__ __launch_bounds__(256, 1)
void gemm2_mma(const __half* __restrict__ Ah, const __half* __restrict__ Al,
               const __half* __restrict__ Bh,
               float* __restrict__ C, int M, int N, int K)
{
    extern __shared__ char sm[];
    const int tid  = threadIdx.x;
    const int lane = tid & 31;
    const int wid  = tid >> 5;
    const int wm   = wid & 1;
    const int wn   = wid >> 1;
    const int m0 = blockIdx.y * 128;
    const int n0 = blockIdx.x * 128;

    const __half* srcs[3] = {Ah, Al, Bh};
    const int r0s[3] = {m0, m0, n0};

    float acc[4][4][4];
#pragma unroll
    for (int i = 0; i < 4; ++i)
#pragma unroll
        for (int j = 0; j < 4; ++j)
#pragma unroll
            for (int q = 0; q < 4; ++q) acc[i][j][q] = 0.0f;

    const int nc = K / BK;

    {
        char* st = sm;
#pragma unroll
        for (int t = 0; t < 3; ++t) {
            const __half* src = srcs[t];
            const int r0 = r0s[t];
            char* dst = st + t * TILE_B;
#pragma unroll
            for (int u = 0; u < 2; ++u) {
                int v = tid + u * 256;
                int row = v >> 2, q = v & 3;
                cp_async16(smem_u32(dst + row * PITCH + q * 16),
                           src + (size_t)(r0 + row) * K + q * 8);
            }
        }
        cp_commit();
    }

    for (int c = 0; c < nc; ++c) {
        if (c + 1 < nc) {
            char* st = sm + ((c + 1) & 1) * STAGE_B;
            const int k0 = (c + 1) * BK;
#pragma unroll
            for (int t = 0; t < 3; ++t) {
                const __half* src = srcs[t];
                const int r0 = r0s[t];
                char* dst = st + t * TILE_B;
#pragma unroll
                for (int u = 0; u < 2; ++u) {
                    int v = tid + u * 256;
                    int row = v >> 2, q = v & 3;
                    cp_async16(smem_u32(dst + row * PITCH + q * 16),
                               src + (size_t)(r0 + row) * K + k0 + q * 8);
                }
            }
            cp_commit();
            cp_wait<1>();
        } else {
            cp_wait<0>();
        }
        __syncthreads();

        char* st = sm + (c & 1) * STAGE_B;
        char* sAh = st;
        char* sAl = st + TILE_B;
        char* sBh = st + 2 * TILE_B;

#pragma unroll
        for (int ks = 0; ks < 2; ++ks) {
            uint32_t ah[4][4], al[4][4];
            const int arow = wm * 64 + (lane & 15);
            const int achk = ks * 2 + (lane >> 4);
#pragma unroll
            for (int i = 0; i < 4; ++i) {
                uint32_t off = (uint32_t)((arow + i * 16) * PITCH + achk * 16);
                ldsm_x4(ah[i][0], ah[i][1], ah[i][2], ah[i][3], smem_u32(sAh + off));
                ldsm_x4(al[i][0], al[i][1], al[i][2], al[i][3], smem_u32(sAl + off));
            }
            uint32_t bh[4][2];
            const int brow = wn * 32 + (lane & 7);
            const int bchk = ks * 2 + ((lane >> 3) & 1);
#pragma unroll
            for (int j = 0; j < 4; ++j) {
                uint32_t off = (uint32_t)((brow + j * 8) * PITCH + bchk * 16);
                ldsm_x2(bh[j][0], bh[j][1], smem_u32(sBh + off));
            }
#pragma unroll
            for (int i = 0; i < 4; ++i)
#pragma unroll
                for (int j = 0; j < 4; ++j) {
                    mma_f16(acc[i][j], ah[i], bh[j]);
                    mma_f16(acc[i][j], al[i], bh[j]);
                }
        }
        __syncthreads();
    }

#pragma unroll
    for (int i = 0; i < 4; ++i) {
        int row = m0 + wm * 64 + i * 16 + (lane >> 2);
#pragma unroll
        for (int j = 0; j < 4; ++j) {
            int col = n0 + wn * 32 + j * 8 + (lane & 3) * 2;
            *(float2*)(C + (size_t)row * N + col) =
                make_float2(acc[i][j][0], acc[i][j][1]);
            *(float2*)(C + (size_t)(row + 8) * N + col) =
                make_float2(acc[i][j][2], acc[i][j][3]);
        }
    }
}

// ---------------------------------------------------------------------------
// fp16 split-2 causal flash attention, GQA. 128 threads (4 warps).
// S = (Qh+Ql) Kh^T; O += (Ph+Pl) Vh. K/V single fp16; 2-stage cp.async.
// ---------------------------------------------------------------------------
#define AP 144                           // smem row pitch (64 fp16 + pad)
#define ATILE (64 * AP)                  // 9216 B
#define ASTAGE (2 * ATILE)               // Kh, Vh
#define AQ_B  (2 * ATILE)                // Qh, Ql
#define ATTN_SMEM (AQ_B + 2 * ASTAGE)    // 55296 B

__global__ __launch_bounds__(128)
void attn_mma(const __half* __restrict__ Qh_g, const __half* __restrict__ Ql_g,
              const __half* __restrict__ Kh_g, const __half* __restrict__ Vh_g,
              __half* __restrict__ Oh_g, __half* __restrict__ Ol_g)
{
    extern __shared__ char sm[];
    char* sQ  = sm;

    const int tid  = threadIdx.x;
    const int lane = tid & 31;
    const int w    = tid >> 5;
    const int qt   = blockIdx.x;
    const int h    = blockIdx.y;
    const int b    = blockIdx.z;
    const int g    = h >> 2;
    const int q0   = qt * 64;

    const int lam = lane & 3;
    const int rho = lane >> 2;

    // ---- prologue: Q (hi/lo) + stage 0 of K/V ----
    {
        const __half* qs[2] = {Qh_g, Ql_g};
#pragma unroll
        for (int u = 0; u < 8; ++u) {
            int idx = tid + u * 128;            // 0..1023
            int t = idx >> 9, rem = idx & 511;
            int row = rem >> 3, c = rem & 7;
            cp_async16(smem_u32(sQ + t * ATILE + row * AP + c * 16),
                       qs[t] + ((size_t)(b * SEQ + q0 + row) * NH + h) * HD + c * 8);
        }
        const __half* ks[2] = {Kh_g, Vh_g};
        char* stg = sm + AQ_B;
#pragma unroll
        for (int u = 0; u < 8; ++u) {
            int idx = tid + u * 128;
            int t = idx >> 9, rem = idx & 511;
            int row = rem >> 3, c = rem & 7;
            cp_async16(smem_u32(stg + t * ATILE + row * AP + c * 16),
                       ks[t] + ((size_t)(b * SEQ + row) * NKV + g) * HD + c * 8);
        }
        cp_commit();
    }

    uint32_t qh[4][4], ql[4][4];
    float m[2] = {-1e30f, -1e30f};
    float l[2] = {0.0f, 0.0f};
    float o[8][4];
#pragma unroll
    for (int j = 0; j < 8; ++j)
#pragma unroll
        for (int e = 0; e < 4; ++e) o[j][e] = 0.0f;

    for (int jt = 0; jt <= qt; ++jt) {
        if (jt < qt) {
            const __half* ks[2] = {Kh_g, Vh_g};
            char* stg = sm + AQ_B + ((jt + 1) & 1) * ASTAGE;
            const int n0 = (jt + 1) * 64;
#pragma unroll
            for (int u = 0; u < 8; ++u) {
                int idx = tid + u * 128;
                int t = idx >> 9, rem = idx & 511;
                int row = rem >> 3, c = rem & 7;
                cp_async16(smem_u32(stg + t * ATILE + row * AP + c * 16),
                           ks[t] + ((size_t)(b * SEQ + n0 + row) * NKV + g) * HD + c * 8);
            }
            cp_commit();
            cp_wait<1>();
        } else {
            cp_wait<0>();
        }
        __syncthreads();

        if (jt == 0) {
#pragma unroll
            for (int kk = 0; kk < 4; ++kk) {
                uint32_t off = (uint32_t)((16 * w + (lane & 15)) * AP +
                                          kk * 32 + (lane >> 4) * 16);
                ldsm_x4(qh[kk][0], qh[kk][1], qh[kk][2], qh[kk][3],
                        smem_u32(sQ + off));
                ldsm_x4(ql[kk][0], ql[kk][1], ql[kk][2], ql[kk][3],
                        smem_u32(sQ + ATILE + off));
            }
        }

        char* stg = sm + AQ_B + (jt & 1) * ASTAGE;
        char* sKh = stg;
        char* sVh = stg + ATILE;

        // ---- S = Q K^T (2 passes) ----
        float s[8][4];
#pragma unroll
        for (int j = 0; j < 8; ++j) {
            s[j][0] = s[j][1] = s[j][2] = s[j][3] = 0.0f;
            uint32_t boff = (uint32_t)((8 * j + (lane & 7)) * AP +
                                       ((lane >> 3) & 3) * 16);
            uint32_t kh[8];
            ldsm_x4(kh[0], kh[1], kh[2], kh[3], smem_u32(sKh + boff));
            ldsm_x4(kh[4], kh[5], kh[6], kh[7], smem_u32(sKh + boff + 64));
#pragma unroll
            for (int kk = 0; kk < 4; ++kk) {
                mma_f16(s[j], qh[kk], &kh[kk * 2]);
                mma_f16(s[j], ql[kk], &kh[kk * 2]);
            }
        }

        // ---- mask + online softmax ----
        if (jt == qt) {
            const int r0 = 16 * w + rho;
#pragma unroll
            for (int j = 0; j < 8; ++j) {
                int c0 = 8 * j + 2 * lam;
                if (c0 > r0)     s[j][0] = -1e30f;
                if (c0 + 1 > r0) s[j][1] = -1e30f;
                if (c0 > r0 + 8)     s[j][2] = -1e30f;
                if (c0 + 1 > r0 + 8) s[j][3] = -1e30f;
            }
        }
#pragma unroll
        for (int r = 0; r < 2; ++r) {
            float loc = -1e30f;
#pragma unroll
            for (int j = 0; j < 8; ++j)
                loc = fmaxf(loc, fmaxf(s[j][r * 2], s[j][r * 2 + 1]));
            loc = fmaxf(loc, __shfl_xor_sync(0xffffffffu, loc, 1));
            loc = fmaxf(loc, __shfl_xor_sync(0xffffffffu, loc, 2));
            float mnew = fmaxf(m[r], loc);
            float sf = __expf(m[r] - mnew);
            float ps = 0.0f;
#pragma unroll
            for (int j = 0; j < 8; ++j) {
                float p0 = __expf(s[j][r * 2]     - mnew);
                float p1 = __expf(s[j][r * 2 + 1] - mnew);
                s[j][r * 2] = p0; s[j][r * 2 + 1] = p1;
                ps += p0 + p1;
            }
            ps += __shfl_xor_sync(0xffffffffu, ps, 1);
            ps += __shfl_xor_sync(0xffffffffu, ps, 2);
            l[r] = l[r] * sf + ps;
            m[r] = mnew;
#pragma unroll
            for (int j = 0; j < 8; ++j) {
                o[j][r * 2]     *= sf;
                o[j][r * 2 + 1] *= sf;
            }
        }

        // ---- P fragments (fp16 hi/lo, in registers) ----
        uint32_t ph[4][4], pl[4][4];
#pragma unroll
        for (int kk = 0; kk < 4; ++kk) {
            float* t0 = s[2 * kk];
            float* t1 = s[2 * kk + 1];
            float e[8] = {t0[0], t0[1], t0[2], t0[3], t1[0], t1[1], t1[2], t1[3]};
            float hi[8], lo[8];
#pragma unroll
            for (int q = 0; q < 8; ++q) {
                __half hb = __float2half_rn(e[q]);
                hi[q] = __half2float(hb);
                lo[q] = e[q] - hi[q];
            }
            ph[kk][0] = pack_h2(hi[0], hi[1]);
            ph[kk][1] = pack_h2(hi[2], hi[3]);
            ph[kk][2] = pack_h2(hi[4], hi[5]);
            ph[kk][3] = pack_h2(hi[6], hi[7]);
            pl[kk][0] = pack_h2(lo[0], lo[1]);
            pl[kk][1] = pack_h2(lo[2], lo[3]);
            pl[kk][2] = pack_h2(lo[4], lo[5]);
            pl[kk][3] = pack_h2(lo[6], lo[7]);
        }

        // ---- O += P V (2 passes) ----
#pragma unroll
        for (int p2 = 0; p2 < 4; ++p2) {
#pragma unroll
            for (int kk = 0; kk < 4; ++kk) {
                uint32_t voff = (uint32_t)((16 * kk + (lane & 15)) * AP +
                                           (2 * p2 + (lane >> 4)) * 16);
                uint32_t vh[4];
                ldsm_x4_t(vh[0], vh[1], vh[2], vh[3], smem_u32(sVh + voff));
                mma_f16(o[2 * p2],     ph[kk], &vh[0]);
                mma_f16(o[2 * p2],     pl[kk], &vh[0]);
                mma_f16(o[2 * p2 + 1], ph[kk], &vh[2]);
                mma_f16(o[2 * p2 + 1], pl[kk], &vh[2]);
            }
        }
        __syncthreads();
    }

    // ---- epilogue: normalize, fp16 hi/lo split, store ----
    float inv0 = 1.0f / l[0];
    float inv1 = 1.0f / l[1];
    const int row0 = q0 + 16 * w + rho;
#pragma unroll
    for (int j = 0; j < 8; ++j) {
        int col = 8 * j + 2 * lam;
        size_t o0 = ((size_t)(b * SEQ + row0) * NH + h) * HD + col;
        size_t o1 = ((size_t)(b * SEQ + row0 + 8) * NH + h) * HD + col;
        float v00 = o[j][0] * inv0, v01 = o[j][1] * inv0;
        float v10 = o[j][2] * inv1, v11 = o[j][3] * inv1;
        float h00 = __half2float(__float2half_rn(v00));
        float h01 = __half2float(__float2half_rn(v01));
        float h10 = __half2float(__float2half_rn(v10));
        float h11 = __half2float(__float2half_rn(v11));
        *(uint32_t*)(Oh_g + o0) = pack_h2(h00, h01);
        *(uint32_t*)(Ol_g + o0) = pack_h2(v00 - h00, v01 - h01);
        *(uint32_t*)(Oh_g + o1) = pack_h2(h10, h11);
        *(uint32_t*)(Ol_g + o1) = pack_h2(v10 - h10, v11 - h11);
    }
}

// ---------------------------------------------------------------------------
extern "C" void kernel_launch(void* const* d_in, const int* in_sizes, int n_in,
                              void* d_out, int out_size)
{
    const float* x  = (const float*)d_in[0];
    const float* Wq = (const float*)d_in[1];
    const float* Wk = (const float*)d_in[2];
    const float* Wv = (const float*)d_in[3];
    const float* Wo = (const float*)d_in[4];
    float* out = (float*)d_out;

    float *Q, *K, *V;
    cudaGetSymbolAddress((void**)&Q, g_Q);
    cudaGetSymbolAddress((void**)&K, g_K);
    cudaGetSymbolAddress((void**)&V, g_V);
    __half *xh, *xl, *wqt, *wkt, *wvt, *wot, *qh, *ql, *kh, *vh;
    cudaGetSymbolAddress((void**)&xh, g_xh);
    cudaGetSymbolAddress((void**)&xl, g_xl);
    cudaGetSymbolAddress((void**)&wqt, g_wqt);
    cudaGetSymbolAddress((void**)&wkt, g_wkt);
    cudaGetSymbolAddress((void**)&wvt, g_wvt);
    cudaGetSymbolAddress((void**)&wot, g_wot);
    cudaGetSymbolAddress((void**)&qh, g_Qh);
    cudaGetSymbolAddress((void**)&ql, g_Ql);
    cudaGetSymbolAddress((void**)&kh, g_Kh);
    cudaGetSymbolAddress((void**)&vh, g_Vh);

    cudaFuncSetAttribute(gemm2_mma, cudaFuncAttributeMaxDynamicSharedMemorySize,
                         GEMM_SMEM);
    cudaFuncSetAttribute(attn_mma, cudaFuncAttributeMaxDynamicSharedMemorySize,
                         ATTN_SMEM);

    const int M = MTOT;           // 4096
    const int NKVD = NKV * HD;    // 512

    // Split x (hi/lo), transpose weights to single fp16
    {
        int n = M * DMODEL;
        split2h_kernel<<<(n + 255) / 256, 256>>>(x, xh, xl, n);
        transh_kernel<<<dim3(DMODEL / 32, DMODEL / 32), dim3(32, 8)>>>(Wq, wqt, DMODEL, DMODEL);
        transh_kernel<<<dim3(NKVD / 32,  DMODEL / 32), dim3(32, 8)>>>(Wk, wkt, DMODEL, NKVD);
        transh_kernel<<<dim3(NKVD / 32,  DMODEL / 32), dim3(32, 8)>>>(Wv, wvt, DMODEL, NKVD);
        transh_kernel<<<dim3(DMODEL / 32, DMODEL / 32), dim3(32, 8)>>>(Wo, wot, DMODEL, DMODEL);
    }

    // QKV projections (fp16 split-2 tensor GEMMs)
    gemm2_mma<<<dim3(DMODEL / 128, M / 128), 256, GEMM_SMEM>>>(xh, xl, wqt, Q, M, DMODEL, DMODEL);
    gemm2_mma<<<dim3(NKVD / 128,  M / 128), 256, GEMM_SMEM>>>(xh, xl, wkt, K, M, NKVD, DMODEL);
    gemm2_mma<<<dim3(NKVD / 128,  M / 128), 256, GEMM_SMEM>>>(xh, xl, wvt, V, M, NKVD, DMODEL);

    // RoPE: Q (scaled, split hi/lo), K (single); V convert
    {
        int totQ = MTOT * NH * 32;
        int totK = MTOT * NKV * 32;
        rope_split_h<<<(totQ + 255) / 256, 256>>>(Q, qh, ql, NH, 0.125f, totQ);
        rope_h<<<(totK + 255) / 256, 256>>>(K, kh, NKV, totK);
        int nV = MTOT * NKVD;
        convh_kernel<<<(nV + 255) / 256, 256>>>(V, vh, nV);
    }

    // Attention; writes fp16 hi/lo of O into xh/xl
    attn_mma<<<dim3(SEQ / 64, NH, BATCH), 128, ATTN_SMEM>>>(qh, ql, kh, vh, xh, xl);

    // Output projection
    gemm2_mma<<<dim3(DMODEL / 128, M / 128), 256, GEMM_SMEM>>>(xh, xl, wot, out, M, DMODEL, DMODEL);
}